// round 13
// baseline (speedup 1.0000x reference)
#include <cuda_runtime.h>
#include <cuda_bf16.h>

#define TT    512
#define BN    8192
#define NTOT  (TT * BN)          // 4,194,304
#define PAIRS (BN / 2)           // 4096
#define NC    32                 // time chunks
#define S     (TT / NC)          // 16 steps per chunk

#define BLK1  128                // pass1 block size (pairs)
#define GRD1  (NC * (PAIRS / BLK1))  // 1024 blocks

#define BLK   256                // pass3 block size
#define GRD   (NC * (BN / BLK))  // 1024 blocks

#define GAMMA_F 0.99f

// Scratch (device globals: allocation-free)
// g_rat: bf16 ratios (sign bit = done), 8 per uint4, layout [c][g][b], g=0,1.
__device__ uint4  g_rat[NC * 2 * BN];      // 8 MB
__device__ float2 g_AB[NC * BN];           // 4 MB, {A,B} per (c,b)
__device__ float  g_part[2 * GRD];
__device__ unsigned int g_ctr;

__device__ __forceinline__ float frcp(float x) {
    float r;
    asm("rcp.approx.f32 %0, %1;" : "=f"(r) : "f"(x));
    return r;
}

// fp32 -> bf16 bits (round-to-nearest-even), ratio >= 0 so bit15 is free
__device__ __forceinline__ unsigned bf16bits(float x) {
    const unsigned u = __float_as_uint(x);
    return (u + 0x7fffu + ((u >> 16) & 1u)) >> 16;
}

// ---------------------------------------------------------------------------
// Pass 1: 2 batch elements/thread; chunk affine map (A,B); bf16 ratio pack.
//   E_exit = A*E_entry + B   (composed ascending in time)
// ---------------------------------------------------------------------------
__global__ void __launch_bounds__(BLK1)
pass1(const float4* __restrict__ prob,    // [T, PAIRS]
      const float4* __restrict__ aprob,
      const float2* __restrict__ v,
      const float2* __restrict__ rew,
      const int2*   __restrict__ act,
      const int2*   __restrict__ dn)
{
    if (blockIdx.x == 0 && threadIdx.x == 0) g_ctr = 0;

    const int c    = blockIdx.x >> 5;
    const int pair = ((blockIdx.x & 31) << 7) + threadIdx.x;
    const int b0   = 2 * pair;
    const int t0   = c * S;

    float A0 = 1.0f, B0 = 0.0f, A1 = 1.0f, B1 = 0.0f;
    unsigned w0[4], w1[4];

    #pragma unroll
    for (int i = 0; i < S; i++) {
        const int idx = (t0 + i) * PAIRS + pair;

        const float4 p  = __ldcs(&prob[idx]);
        const float4 ap = __ldcs(&aprob[idx]);
        const int2   aa = __ldcs(&act[idx]);
        const int2   dd = __ldcs(&dn[idx]);
        const float2 vv = __ldg(&v[idx]);
        const float2 rr = __ldg(&rew[idx]);

        const float pa0  = aa.x ? p.y  : p.x;
        const float apa0 = aa.x ? ap.y : ap.x;
        const float num0 = pa0 * (ap.x + ap.y);
        const float den0 = (p.x + p.y) * apa0;

        const float pa1  = aa.y ? p.w  : p.z;
        const float apa1 = aa.y ? ap.w : ap.z;
        const float num1 = pa1 * (ap.z + ap.w);
        const float den1 = (p.z + p.w) * apa1;

        const float inv  = frcp(den0 * den1);   // one MUFU per 2 elems
        const float rat0 = num0 * den1 * inv;
        const float rat1 = num1 * den0 * inv;

        const float g0   = dd.x ? 0.0f : GAMMA_F;
        const float rho0 = fminf(rat0, 1.0f);
        const float Bt0  = fmaf(rho0, rr.x - vv.x, vv.x);
        B0 = fmaf(A0, Bt0, B0);
        A0 = A0 * (rho0 * g0);

        const float g1   = dd.y ? 0.0f : GAMMA_F;
        const float rho1 = fminf(rat1, 1.0f);
        const float Bt1  = fmaf(rho1, rr.y - vv.y, vv.y);
        B1 = fmaf(A1, Bt1, B1);
        A1 = A1 * (rho1 * g1);

        // bf16 ratio, done bit in bf16 sign
        const unsigned us0 = bf16bits(rat0) | ((unsigned)dd.x << 15);
        const unsigned us1 = bf16bits(rat1) | ((unsigned)dd.y << 15);

        const int word = (i & 7) >> 1;
        if ((i & 1) == 0) { w0[word] = us0;          w1[word] = us1; }
        else              { w0[word] |= us0 << 16;   w1[word] |= us1 << 16; }

        if ((i & 7) == 7) {
            const int base = (c * 2 + (i >> 3)) * BN;
            g_rat[base + b0]     = make_uint4(w0[0], w0[1], w0[2], w0[3]);
            g_rat[base + b0 + 1] = make_uint4(w1[0], w1[1], w1[2], w1[3]);
        }
    }

    *reinterpret_cast<float4*>(&g_AB[c * BN + b0]) =
        make_float4(A0, B0, A1, B1);

    cudaTriggerProgrammaticLaunchCompletion();
}

// ---------------------------------------------------------------------------
// Pass 3 (PDL): grid-dependency sync, batched ratio LDG.128s, in-block
// entry-carry fold, replay, fused deterministic finish.
// ---------------------------------------------------------------------------
__global__ void __launch_bounds__(BLK, 6)
pass3(const float*  __restrict__ v,
      const float*  __restrict__ rew,
      const float*  __restrict__ nv,
      float*        __restrict__ out)
{
    const int c  = blockIdx.x >> 5;
    const int b  = ((blockIdx.x & 31) << 8) + threadIdx.x;
    const int t0 = c * S;

    cudaGridDependencySynchronize();   // wait for pass1's memory

    // batched ratio loads: 16 bf16 ratios in two LDG.128
    const uint4 R0 = __ldg(&g_rat[(c * 2 + 0) * BN + b]);
    const uint4 R1 = __ldg(&g_rat[(c * 2 + 1) * BN + b]);

    // entry carry: right-fold chunk maps NC-1 .. c+1 (L2-hot, fixed order)
    float E = __ldg(&nv[(TT - 1) * BN + b]);
    #pragma unroll 8
    for (int cc = NC - 1; cc > c; cc--) {
        const float2 ab = g_AB[cc * BN + b];
        E = fmaf(ab.x, E, ab.y);
    }

    // replay descending time; v/rew streamed (L2-warm from pass1)
    float actor = 0.0f, critic = 0.0f;
    #pragma unroll
    for (int k = 0; k < S; k++) {
        const int i   = S - 1 - k;
        const int idx = (t0 + i) * BN + b;

        const float vv = __ldg(&v[idx]);
        const float rr = __ldg(&rew[idx]);

        const unsigned* wp = (i >> 3) ? (&R1.x) : (&R0.x);
        const unsigned word = wp[(i & 7) >> 1];
        const unsigned us   = (i & 1) ? (word >> 16) : (word & 0xffffu);
        const float ratio = __uint_as_float((us & 0x7fffu) << 16);
        const float g    = (us >> 15) ? 0.0f : GAMMA_F;
        const float rho  = fminf(ratio, 1.0f);
        const float adv  = rho * (rr + g * E - vv);
        critic = fmaf(adv, adv, critic);
        const float cl = fminf(fmaxf(ratio, 0.8f), 1.2f);
        actor += fminf(ratio * adv, cl * adv);
        E = vv + adv;
    }

    // deterministic block reduction
    __shared__ float sa[8], sc[8];
    #pragma unroll
    for (int o = 16; o > 0; o >>= 1) {
        actor  += __shfl_down_sync(0xffffffffu, actor,  o);
        critic += __shfl_down_sync(0xffffffffu, critic, o);
    }
    const int w = threadIdx.x >> 5;
    if ((threadIdx.x & 31) == 0) { sa[w] = actor; sc[w] = critic; }
    __syncthreads();
    if (threadIdx.x == 0) {
        float Asum = 0.0f, Csum = 0.0f;
        #pragma unroll
        for (int k = 0; k < 8; k++) { Asum += sa[k]; Csum += sc[k]; }
        g_part[blockIdx.x]       = Asum;
        g_part[GRD + blockIdx.x] = Csum;
    }

    // last block: final deterministic reduction
    __shared__ bool is_last;
    if (threadIdx.x == 0) {
        __threadfence();
        is_last = (atomicAdd(&g_ctr, 1u) == (unsigned)(GRD - 1));
    }
    __syncthreads();
    if (is_last) {
        const int t = threadIdx.x;
        __shared__ float ra[BLK], rc[BLK];
        float Asum = 0.0f, Csum = 0.0f;
        #pragma unroll
        for (int k = 0; k < GRD / BLK; k++) {    // fixed order
            Asum += g_part[t + k * BLK];
            Csum += g_part[GRD + t + k * BLK];
        }
        ra[t] = Asum; rc[t] = Csum;
        __syncthreads();
        #pragma unroll
        for (int s = BLK / 2; s > 0; s >>= 1) {
            if (t < s) { ra[t] += ra[t + s]; rc[t] += rc[t + s]; }
            __syncthreads();
        }
        if (t == 0) {
            const float inv = 1.0f / (float)NTOT;
            out[0] = (-ra[0] + 0.5f * rc[0]) * inv;
        }
    }
}

extern "C" void kernel_launch(void* const* d_in, const int* in_sizes, int n_in,
                              void* d_out, int out_size)
{
    const float4* prob  = (const float4*)d_in[0];
    const float4* aprob = (const float4*)d_in[1];
    const float*  v     = (const float*)d_in[2];
    const float*  nv    = (const float*)d_in[3];
    const float*  rew   = (const float*)d_in[4];
    const int*    act   = (const int*)d_in[5];
    const int*    dn    = (const int*)d_in[6];
    float* out = (float*)d_out;

    pass1<<<GRD1, BLK1>>>(prob, aprob,
                          (const float2*)v, (const float2*)rew,
                          (const int2*)act, (const int2*)dn);

    // PDL launch: pass3 scheduled while pass1 drains; device-side
    // cudaGridDependencySynchronize() enforces the data dependency.
    cudaLaunchConfig_t cfg = {};
    cfg.gridDim  = dim3(GRD, 1, 1);
    cfg.blockDim = dim3(BLK, 1, 1);
    cfg.dynamicSmemBytes = 0;
    cfg.stream = 0;
    cudaLaunchAttribute attrs[1];
    attrs[0].id = cudaLaunchAttributeProgrammaticStreamSerialization;
    attrs[0].val.programmaticStreamSerializationAllowed = 1;
    cfg.attrs = attrs;
    cfg.numAttrs = 1;
    cudaLaunchKernelEx(&cfg, pass3, v, rew, nv, out);
}